// round 15
// baseline (speedup 1.0000x reference)
#include <cuda_runtime.h>
#include <cuda_fp16.h>
#include <cstdint>

// Problem constants (MB_projection: B=1024, IN=1024, EXP=40, K=7)
#define B_TOTAL   1024
#define IN_DIM    1024
#define OUT_DIM   40960
#define KNZ       7

// Tiling
#define BC        64                  // batch rows per CTA (32 half2-packed pairs)
#define J32       32
#define O_CTA     1024
#define NTHREADS  1024
#define NWARPS    32
#define O_WARP    4                   // outputs per warp per pass
#define O_PASS    (NWARPS * O_WARP)   // 128
#define NPASS     (O_CTA / O_PASS)    // 8

// smem layout (words)
#define XS_WORDS   (IN_DIM * J32)     // 32768 (half2 per word) = 128 KB
#define META_WORDS (O_CTA * 16)       // 16384 (4 uint4 per output) = 64 KB
#define ST_WORDS   (BC * 128)         // 8192 words = 32 KB single stage buffer
#define SMEM_WORDS (XS_WORDS + META_WORDS + ST_WORDS)
#define SMEM_BYTES (SMEM_WORDS * 4)   // 229,376 B (<= 232,448 B limit)

// Packed metadata per output (64 B = 4 uint4), zero-unpack form:
//   m0 = {off0, off1, off2, off3}   (u32 BYTE offsets = idx*128 into xs)
//   m1 = {off4, off5, off6, pad}
//   m2 = {vd0, vd1, vd2, vd3}       (vdK = half2(vK, vK) pre-duplicated)
//   m3 = {vd4, vd5, vd6, pad}
__device__ uint4   g_meta[OUT_DIM * 4];              // 2.62 MB
// x transposed + fp16-packed: g_xt[c * B/2 + j] = (x[2j][c], x[2j+1][c])
__device__ __half2 g_xt[IN_DIM * (B_TOTAL / 2)];     // 2 MB

static __device__ __forceinline__ unsigned dup_h2(float v) {
    __half2 h = __floats2half2_rn(v, v);
    return reinterpret_cast<unsigned&>(h);
}
static __device__ __forceinline__ __half2 as_h2(unsigned u) {
    return reinterpret_cast<__half2&>(u);
}

// Merged prep: blocks [0,512) transpose+pack x, blocks [512,672) pack metadata.
__global__ void prep_kernel(const float* __restrict__ x,
                            const int* __restrict__ idx,
                            const float* __restrict__ vals) {
    __shared__ float tile[64][33];
    const int bx = blockIdx.x;
    const int t  = threadIdx.x;
    if (bx < 512) {
        const int c0 = (bx & 31) * 32;
        const int r0 = (bx >> 5) * 64;
        const int tx = t & 31;
        const int ty = t >> 5;
        #pragma unroll
        for (int i = 0; i < 8; ++i)
            tile[ty + 8 * i][tx] = x[(size_t)(r0 + ty + 8 * i) * IN_DIM + c0 + tx];
        __syncthreads();
        #pragma unroll
        for (int i = 0; i < 4; ++i) {
            int c = ty + 8 * i;
            float lo = tile[2 * tx + 0][c];
            float hi = tile[2 * tx + 1][c];
            g_xt[(size_t)(c0 + c) * (B_TOTAL / 2) + (r0 >> 1) + tx] = __floats2half2_rn(lo, hi);
        }
    } else {
        const int o = (bx - 512) * 256 + t;          // 160*256 = 40960 exactly
        const int*   ip = idx  + o * KNZ;
        const float* vp = vals + o * KNZ;
        uint4 m0, m1, m2, m3;
        m0.x = (unsigned)ip[0] * 128u;   // byte offset into xs: idx * 32 half2 * 4 B
        m0.y = (unsigned)ip[1] * 128u;
        m0.z = (unsigned)ip[2] * 128u;
        m0.w = (unsigned)ip[3] * 128u;
        m1.x = (unsigned)ip[4] * 128u;
        m1.y = (unsigned)ip[5] * 128u;
        m1.z = (unsigned)ip[6] * 128u;
        m1.w = 0u;
        m2.x = dup_h2(vp[0]); m2.y = dup_h2(vp[1]);
        m2.z = dup_h2(vp[2]); m2.w = dup_h2(vp[3]);
        m3.x = dup_h2(vp[4]); m3.y = dup_h2(vp[5]);
        m3.z = dup_h2(vp[6]); m3.w = 0u;
        g_meta[o * 4 + 0] = m0;
        g_meta[o * 4 + 1] = m1;
        g_meta[o * 4 + 2] = m2;
        g_meta[o * 4 + 3] = m3;
    }
}

__global__ __launch_bounds__(NTHREADS, 1)
void mb_proj_kernel(float* __restrict__ y) {
    extern __shared__ unsigned int smem[];
    __half2* xs    = reinterpret_cast<__half2*>(smem);            // [IN][32] half2
    uint4*   meta  = reinterpret_cast<uint4*>(smem + XS_WORDS);   // [O_CTA][4]
    float*   stage = reinterpret_cast<float*>(smem + XS_WORDS + META_WORDS); // swizzled [64][128]

    const int t     = threadIdx.x;
    const int lane  = t & 31;
    const int w     = t >> 5;                 // 0..31
    const int o_cta = blockIdx.x * O_CTA;
    const int b0    = blockIdx.y * BC;

    // ---- meta fill: coalesced LDG.128 -> STS.128 (4 iters) ----
    {
        const uint4* src = g_meta + (size_t)blockIdx.x * (O_CTA * 4);
        #pragma unroll
        for (int i = 0; i < (O_CTA * 4) / NTHREADS; ++i)
            meta[t + i * NTHREADS] = src[t + i * NTHREADS];
    }
    // ---- x tile fill: coalesced LDG.128 -> conflict-free STS.128 (8 iters) ----
    {
        const uint4* xsrc = reinterpret_cast<const uint4*>(g_xt);
        uint4*       xdst = reinterpret_cast<uint4*>(xs);
        const int jq    = t & 7;              // uint4 slot within 32-half2 row
        const int cbase = t >> 3;             // 0..127
        const int boff  = b0 >> 3;            // uint4 offset of batch window
        #pragma unroll
        for (int i = 0; i < 8; ++i) {
            int c = cbase + 128 * i;
            xdst[c * 8 + jq] = xsrc[(size_t)c * 128 + boff + jq];
        }
    }
    __syncthreads();

    // per-lane gather base in BYTES: lane = row-pair j occupies bank j
    const char* xbb = reinterpret_cast<const char*>(xs) + lane * 4;
    const int   sz  = (lane & 7) << 2;        // stage XOR swizzle

    for (int p = 0; p < NPASS; ++p) {
        // ---- compute 4 outputs for this warp (zero-unpack meta, HFMA2 math) ----
        float ax[4], ay[4];                   // .x -> row 2*lane, .y -> row 2*lane+1
        const uint4* mp = meta + (p * O_PASS + w * O_WARP) * 4;
        #pragma unroll
        for (int e = 0; e < 4; ++e) {
            uint4 m0 = mp[e * 4 + 0];         // 4 broadcast LDS.128
            uint4 m1 = mp[e * 4 + 1];
            uint4 m2 = mp[e * 4 + 2];
            uint4 m3 = mp[e * 4 + 3];
            // 7 conflict-free LDS.32 gathers (1 IADD3 each), 7 HFMA2 (2 rows each)
            __half2 x0 = *reinterpret_cast<const __half2*>(xbb + m0.x);
            __half2 x1 = *reinterpret_cast<const __half2*>(xbb + m0.y);
            __half2 x2 = *reinterpret_cast<const __half2*>(xbb + m0.z);
            __half2 x3 = *reinterpret_cast<const __half2*>(xbb + m0.w);
            __half2 x4 = *reinterpret_cast<const __half2*>(xbb + m1.x);
            __half2 x5 = *reinterpret_cast<const __half2*>(xbb + m1.y);
            __half2 x6 = *reinterpret_cast<const __half2*>(xbb + m1.z);
            __half2 acc0 = __hmul2(as_h2(m2.x), x0);
            __half2 acc1 = __hmul2(as_h2(m2.y), x1);
            acc0 = __hfma2(as_h2(m2.z), x2, acc0);
            acc1 = __hfma2(as_h2(m2.w), x3, acc1);
            acc0 = __hfma2(as_h2(m3.x), x4, acc0);
            acc1 = __hfma2(as_h2(m3.y), x5, acc1);
            acc0 = __hfma2(as_h2(m3.z), x6, acc0);
            float2 f0 = __half22float2(acc0);
            float2 f1 = __half22float2(acc1);
            ax[e] = f0.x + f1.x;
            ay[e] = f0.y + f1.y;
        }

        // ---- XOR-swizzled stage writes (STS.128, conflict-free per 8-lane phase) ----
        {
            const int cc = w * O_WARP;
            const int w0 = ((2 * lane) * 128 + cc) ^ sz;
            const int w1 = ((2 * lane + 1) * 128 + cc) ^ sz;
            *reinterpret_cast<float4*>(stage + w0) = make_float4(ax[0], ax[1], ax[2], ax[3]);
            *reinterpret_cast<float4*>(stage + w1) = make_float4(ay[0], ay[1], ay[2], ay[3]);
        }
        __syncthreads();

        // ---- store: 2 rows per warp, conflict-free LDS.128 -> 512B coalesced STG.128 ----
        #pragma unroll
        for (int s = 0; s < 2; ++s) {
            const int r  = w * 2 + s;
            const int wd = (r * 128 + 4 * lane) ^ (((r >> 1) & 7) << 2);
            float4 v = *reinterpret_cast<const float4*>(stage + wd);
            size_t off = (size_t)(b0 + r) * OUT_DIM + (size_t)(o_cta + p * O_PASS) + 4 * lane;
            __stcs(reinterpret_cast<float4*>(y + off), v);
        }
        __syncthreads();   // stage reused next pass
    }
}

extern "C" void kernel_launch(void* const* d_in, const int* in_sizes, int n_in,
                              void* d_out, int out_size) {
    const float* x    = (const float*)d_in[0];   // [B, IN] f32
    const float* vals = (const float*)d_in[1];   // [OUT, K] f32
    const int*   idx  = (const int*)d_in[2];     // [OUT, K] i32
    float*       y    = (float*)d_out;           // [B, OUT] f32

    prep_kernel<<<512 + OUT_DIM / 256, 256>>>(x, idx, vals);   // 672 blocks

    cudaFuncSetAttribute(mb_proj_kernel, cudaFuncAttributeMaxDynamicSharedMemorySize, SMEM_BYTES);
    dim3 grid(OUT_DIM / O_CTA, B_TOTAL / BC);    // (40, 16) = 640 CTAs
    mb_proj_kernel<<<grid, NTHREADS, SMEM_BYTES>>>(y);
}

// round 17
// speedup vs baseline: 1.3491x; 1.3491x over previous
#include <cuda_runtime.h>
#include <cuda_fp16.h>
#include <cstdint>

// Problem constants (MB_projection: B=1024, IN=1024, EXP=40, K=7)
#define B_TOTAL   1024
#define IN_DIM    1024
#define OUT_DIM   40960
#define KNZ       7

// Tiling
#define BC        64                  // batch rows per CTA (32 half2-packed pairs)
#define J32       32
#define O_CTA     640                 // outputs per CTA -> grid (64,16)=1024 CTAs, ~6.9 waves
#define NTHREADS  1024
#define NWARPS    32
#define O_WARP    4                   // outputs per warp per pass
#define O_PASS    (NWARPS * O_WARP)   // 128
#define NPASS     (O_CTA / O_PASS)    // 5

// smem layout (words)
#define XS_WORDS   (IN_DIM * J32)     // 32768 (half2 per word) = 128 KB
#define META_WORDS (O_CTA * 8)        // 5120  (2 uint4 per output) = 20 KB
#define ST_ONE     (BC * 128)         // 8192 words = 32 KB per stage buffer
#define SMEM_WORDS (XS_WORDS + META_WORDS + 2 * ST_ONE)
#define SMEM_BYTES (SMEM_WORDS * 4)   // 217,088 B (< 232,448 B limit)

// Packed metadata per output (32 B = 2 uint4):
//   m0 = {i0*32|i1*32<<16, i2*32|i3*32<<16, i4*32|i5*32<<16, i6*32}  (u16, premultiplied by 32)
//   m1 = {h2(v0,v1), h2(v2,v3), h2(v4,v5), h2(v6,0)}                 (fp16 vals)
__device__ uint4   g_meta[OUT_DIM * 2];              // 1.31 MB
// x transposed + fp16-packed: g_xt[c * B/2 + j] = (x[2j][c], x[2j+1][c])
__device__ __half2 g_xt[IN_DIM * (B_TOTAL / 2)];     // 2 MB

static __device__ __forceinline__ unsigned pack_h2(float a, float b) {
    __half2 h = __floats2half2_rn(a, b);
    return reinterpret_cast<unsigned&>(h);
}

// Merged prep: blocks [0,512) transpose+pack x, blocks [512,672) pack metadata.
__global__ void prep_kernel(const float* __restrict__ x,
                            const int* __restrict__ idx,
                            const float* __restrict__ vals) {
    __shared__ float tile[64][33];
    const int bx = blockIdx.x;
    const int t  = threadIdx.x;
    if (bx < 512) {
        const int c0 = (bx & 31) * 32;
        const int r0 = (bx >> 5) * 64;
        const int tx = t & 31;
        const int ty = t >> 5;
        #pragma unroll
        for (int i = 0; i < 8; ++i)
            tile[ty + 8 * i][tx] = x[(size_t)(r0 + ty + 8 * i) * IN_DIM + c0 + tx];
        __syncthreads();
        #pragma unroll
        for (int i = 0; i < 4; ++i) {
            int c = ty + 8 * i;
            float lo = tile[2 * tx + 0][c];
            float hi = tile[2 * tx + 1][c];
            g_xt[(size_t)(c0 + c) * (B_TOTAL / 2) + (r0 >> 1) + tx] = __floats2half2_rn(lo, hi);
        }
    } else {
        const int o = (bx - 512) * 256 + t;          // 160*256 = 40960 exactly
        const int*   ip = idx  + o * KNZ;
        const float* vp = vals + o * KNZ;
        uint4 m0, m1;
        m0.x = ((unsigned)ip[0] * 32u) | (((unsigned)ip[1] * 32u) << 16);
        m0.y = ((unsigned)ip[2] * 32u) | (((unsigned)ip[3] * 32u) << 16);
        m0.z = ((unsigned)ip[4] * 32u) | (((unsigned)ip[5] * 32u) << 16);
        m0.w = (unsigned)ip[6] * 32u;
        m1.x = pack_h2(vp[0], vp[1]);
        m1.y = pack_h2(vp[2], vp[3]);
        m1.z = pack_h2(vp[4], vp[5]);
        m1.w = pack_h2(vp[6], 0.0f);
        g_meta[o * 2 + 0] = m0;
        g_meta[o * 2 + 1] = m1;
    }
}

__global__ __launch_bounds__(NTHREADS, 1)
void mb_proj_kernel(float* __restrict__ y) {
    extern __shared__ unsigned int smem[];
    __half2* xs    = reinterpret_cast<__half2*>(smem);            // [IN][32] half2
    uint4*   meta  = reinterpret_cast<uint4*>(smem + XS_WORDS);   // [O_CTA][2]
    float*   stage = reinterpret_cast<float*>(smem + XS_WORDS + META_WORDS); // 2 x swizzled [64][128]

    const int t     = threadIdx.x;
    const int lane  = t & 31;
    const int w     = t >> 5;                 // 0..31
    const int o_cta = blockIdx.x * O_CTA;
    const int b0    = blockIdx.y * BC;

    // ---- meta fill: coalesced LDG.128 -> STS.128 (1280 uint4, 2 predicated iters) ----
    {
        const uint4* src = g_meta + (size_t)blockIdx.x * (O_CTA * 2);
        #pragma unroll
        for (int i = 0; i < 2; ++i) {
            int m = t + i * NTHREADS;
            if (m < O_CTA * 2) meta[m] = src[m];
        }
    }
    // ---- x tile fill: coalesced LDG.128 -> conflict-free STS.128 (8 iters) ----
    {
        const uint4* xsrc = reinterpret_cast<const uint4*>(g_xt);
        uint4*       xdst = reinterpret_cast<uint4*>(xs);
        const int jq    = t & 7;              // uint4 slot within 32-half2 row
        const int cbase = t >> 3;             // 0..127
        const int boff  = b0 >> 3;            // uint4 offset of batch window
        #pragma unroll
        for (int i = 0; i < 8; ++i) {
            int c = cbase + 128 * i;
            xdst[c * 8 + jq] = xsrc[(size_t)c * 128 + boff + jq];
        }
    }
    __syncthreads();

    const __half2* xb = xs + lane;            // lane = row-pair j; gather bank conflict-free
    const int      sz = (lane & 7) << 2;      // stage XOR swizzle

    for (int p = 0; p < NPASS; ++p) {
        // ---- store previous pass (drains old buffer while this pass computes) ----
        if (p > 0) {
            const float* buf = stage + ((p - 1) & 1) * ST_ONE;
            #pragma unroll
            for (int s = 0; s < 2; ++s) {
                const int r  = w * 2 + s;
                const int wd = (r * 128 + 4 * lane) ^ (((r >> 1) & 7) << 2);
                float4 v = *reinterpret_cast<const float4*>(buf + wd);
                size_t off = (size_t)(b0 + r) * OUT_DIM + (size_t)(o_cta + (p - 1) * O_PASS) + 4 * lane;
                __stcs(reinterpret_cast<float4*>(y + off), v);
            }
        }

        // ---- compute 4 outputs for this warp (packed fp16 math, fp32 combine) ----
        float ax[4], ay[4];                   // .x -> row 2*lane, .y -> row 2*lane+1
        const uint4* mp = meta + (p * O_PASS + w * O_WARP) * 2;
        #pragma unroll
        for (int e = 0; e < 4; ++e) {
            uint4 m0 = mp[e * 2 + 0];         // 2 broadcast LDS.128
            uint4 m1 = mp[e * 2 + 1];
            int i0 = m0.x & 0xFFFF, i1 = m0.x >> 16;
            int i2 = m0.y & 0xFFFF, i3 = m0.y >> 16;
            int i4 = m0.z & 0xFFFF, i5 = m0.z >> 16;
            int i6 = m0.w;                    // high bits already zero
            __half2 w01 = *reinterpret_cast<const __half2*>(&m1.x);
            __half2 w23 = *reinterpret_cast<const __half2*>(&m1.y);
            __half2 w45 = *reinterpret_cast<const __half2*>(&m1.z);
            __half2 w6_ = *reinterpret_cast<const __half2*>(&m1.w);
            __half2 v0d = __low2half2(w01),  v1d = __high2half2(w01);
            __half2 v2d = __low2half2(w23),  v3d = __high2half2(w23);
            __half2 v4d = __low2half2(w45),  v5d = __high2half2(w45);
            __half2 v6d = __low2half2(w6_);
            // 7 conflict-free LDS.32 gathers feeding 7 HFMA2 (2 rows each),
            // split into two chains (4 + 3 terms) combined in fp32.
            __half2 acc0 = __hmul2(v0d, xb[i0]);
            __half2 acc1 = __hmul2(v1d, xb[i1]);
            acc0 = __hfma2(v2d, xb[i2], acc0);
            acc1 = __hfma2(v3d, xb[i3], acc1);
            acc0 = __hfma2(v4d, xb[i4], acc0);
            acc1 = __hfma2(v5d, xb[i5], acc1);
            acc0 = __hfma2(v6d, xb[i6], acc0);
            float2 f0 = __half22float2(acc0);
            float2 f1 = __half22float2(acc1);
            ax[e] = f0.x + f1.x;
            ay[e] = f0.y + f1.y;
        }

        // ---- XOR-swizzled stage writes (STS.128, conflict-free per 8-lane phase) ----
        {
            float* buf = stage + (p & 1) * ST_ONE;
            const int cc = w * O_WARP;
            const int w0 = ((2 * lane) * 128 + cc) ^ sz;
            const int w1 = ((2 * lane + 1) * 128 + cc) ^ sz;
            *reinterpret_cast<float4*>(buf + w0) = make_float4(ax[0], ax[1], ax[2], ax[3]);
            *reinterpret_cast<float4*>(buf + w1) = make_float4(ay[0], ay[1], ay[2], ay[3]);
        }
        __syncthreads();   // single barrier per pass (double-buffered stage)
    }

    // ---- drain final pass ----
    {
        const float* buf = stage + ((NPASS - 1) & 1) * ST_ONE;
        #pragma unroll
        for (int s = 0; s < 2; ++s) {
            const int r  = w * 2 + s;
            const int wd = (r * 128 + 4 * lane) ^ (((r >> 1) & 7) << 2);
            float4 v = *reinterpret_cast<const float4*>(buf + wd);
            size_t off = (size_t)(b0 + r) * OUT_DIM + (size_t)(o_cta + (NPASS - 1) * O_PASS) + 4 * lane;
            __stcs(reinterpret_cast<float4*>(y + off), v);
        }
    }
}

extern "C" void kernel_launch(void* const* d_in, const int* in_sizes, int n_in,
                              void* d_out, int out_size) {
    const float* x    = (const float*)d_in[0];   // [B, IN] f32
    const float* vals = (const float*)d_in[1];   // [OUT, K] f32
    const int*   idx  = (const int*)d_in[2];     // [OUT, K] i32
    float*       y    = (float*)d_out;           // [B, OUT] f32

    prep_kernel<<<512 + OUT_DIM / 256, 256>>>(x, idx, vals);   // 672 blocks

    cudaFuncSetAttribute(mb_proj_kernel, cudaFuncAttributeMaxDynamicSharedMemorySize, SMEM_BYTES);
    dim3 grid(OUT_DIM / O_CTA, B_TOTAL / BC);    // (64, 16) = 1024 CTAs
    mb_proj_kernel<<<grid, NTHREADS, SMEM_BYTES>>>(y);
}